// round 14
// baseline (speedup 1.0000x reference)
#include <cuda_runtime.h>
#include <cuda_fp16.h>

#define SEQ 4096
#define HID 1024
#define NCTA 128
#define CSTRIDE 32
#define NSLOT 16
#define NREG 4           // register-resident chains per warp (rest in SMEM)

// ---------------- device scratch ----------------
__device__ float  g_Zu[SEQ * HID];
__device__ float  g_Zr[SEQ * HID];
__device__ float  g_Zc[SEQ * HID];
__device__ __half g_Hh[4][SEQ * HID];      // fp16 hidden-state exchange
__device__ int    g_ctr[4][NSLOT * CSTRIDE];

__global__ void reset_ctrs_kernel() {
    int i = blockIdx.x * blockDim.x + threadIdx.x;
    if (i < 4 * NSLOT * CSTRIDE) ((int*)g_ctr)[i] = 0;
}

// ---------------- memory helpers (proven sync primitives) ----------------
__device__ __forceinline__ uint4 ldcg4u(const uint4* p) {
    uint4 v;
    asm volatile("ld.global.cg.v4.u32 {%0,%1,%2,%3},[%4];"
                 : "=r"(v.x), "=r"(v.y), "=r"(v.z), "=r"(v.w) : "l"(p) : "memory");
    return v;
}
__device__ __forceinline__ void stcg_h(__half* p, __half v) {
    unsigned short b = *(unsigned short*)&v;
    asm volatile("st.global.cg.u16 [%0],%1;" :: "l"(p), "h"(b) : "memory");
}
__device__ __forceinline__ int ldacq(const int* p) {
    int v;
    asm volatile("ld.acquire.gpu.global.s32 %0,[%1];" : "=r"(v) : "l"(p) : "memory");
    return v;
}
__device__ __forceinline__ void red_release_add(int* p, int v) {
    asm volatile("red.release.gpu.global.add.s32 [%0],%1;" :: "l"(p), "r"(v) : "memory");
}
__device__ __forceinline__ float sigf(float x) { return 1.f / (1.f + __expf(-x)); }

__device__ __forceinline__ unsigned pack_h2(float a, float b) {
    __half2 h = __floats2half2_rn(a, b);
    return *(unsigned*)&h;
}
// fp16 SIMD dot of 8 elems, fp32 result
__device__ __forceinline__ float dot4u(const uint4& wv, const uint4& hv) {
    const __half2* w = (const __half2*)&wv;
    const __half2* h = (const __half2*)&hv;
    __half2 acc = __hmul2(w[0], h[0]);
    acc = __hfma2(w[1], h[1], acc);
    acc = __hfma2(w[2], h[2], acc);
    acc = __hfma2(w[3], h[3], acc);
    float2 f = __half22float2(acc);
    return f.x + f.y;
}

// ---------------- fp32 SGEMM batch (layer-0 input projections) -------------
struct GemmJob { const float* A; const float* B; float* C; };
__global__ __launch_bounds__(256) void sgemm_nt_batch(GemmJob j0, GemmJob j1, GemmJob j2) {
    const GemmJob job = (blockIdx.z == 0) ? j0 : (blockIdx.z == 1) ? j1 : j2;
    const float* __restrict__ A = job.A;
    const float* __restrict__ B = job.B;
    float* __restrict__ C = job.C;
    const int K = HID, N = HID;
    __shared__ float As[8][128];
    __shared__ float Bs[8][128];
    const int tid = threadIdx.x;
    const int m0 = blockIdx.y * 128;
    const int n0 = blockIdx.x * 128;
    const int tx = tid & 15;
    const int ty = tid >> 4;
    const int lrow = tid >> 1;
    const int kp = (tid & 1) * 4;

    const float* Ap = A + (m0 + lrow) * K + kp;
    const float* Bp = B + (n0 + lrow) * K + kp;

    float acc[8][8];
#pragma unroll
    for (int i = 0; i < 8; i++)
#pragma unroll
        for (int j = 0; j < 8; j++) acc[i][j] = 0.f;

    for (int k0 = 0; k0 < K; k0 += 8) {
        float4 av = *(const float4*)(Ap + k0);
        float4 bv = *(const float4*)(Bp + k0);
        __syncthreads();
        As[kp + 0][lrow] = av.x; As[kp + 1][lrow] = av.y;
        As[kp + 2][lrow] = av.z; As[kp + 3][lrow] = av.w;
        Bs[kp + 0][lrow] = bv.x; Bs[kp + 1][lrow] = bv.y;
        Bs[kp + 2][lrow] = bv.z; Bs[kp + 3][lrow] = bv.w;
        __syncthreads();
#pragma unroll
        for (int kk = 0; kk < 8; kk++) {
            float a[8], b[8];
#pragma unroll
            for (int i = 0; i < 8; i++) a[i] = As[kk][ty * 8 + i];
#pragma unroll
            for (int j = 0; j < 8; j++) b[j] = Bs[kk][tx * 8 + j];
#pragma unroll
            for (int i = 0; i < 8; i++)
#pragma unroll
                for (int j = 0; j < 8; j++) acc[i][j] = fmaf(a[i], b[j], acc[i][j]);
        }
    }
#pragma unroll
    for (int i = 0; i < 8; i++) {
        float* Cp = C + (m0 + ty * 8 + i) * N + n0 + tx * 8;
#pragma unroll
        for (int j = 0; j < 8; j++) Cp[j] = acc[i][j];
    }
}

// ---------------- quad-layer fused GRU scan, instance-local gates ----------
// 128 CTAs x 512 threads (16 warps). Warp w owns instances 2w, 2w+1 (both
// layer l = w>>2). l0 instances have 3 chains (u,r,c), others 5 (u,r,c,s,q).
// Round R: layer l computes t=R-l. Warps 0-3 poll + RAW-copy fp16 h rows
// into ping-pong SMEM; ONE __syncthreads; every warp runs its chains with
// full 5-shfl reduces (sums in all lanes); lanes 0/1 compute their
// instance's gates inline and publish (st.cg fp16 + red.release). No barB.
struct QuadArgs {
    const float *Wu, *Wr, *Wc, *Bu, *Br, *Bc, *Uh, *Uhr, *Zu, *Zr, *Zc;
    __half *H;
    float *out;
    int *ctr;
};

#define WROW_BYTES (96 * 2048)
#define HBUF_BYTES (2 * 4 * 2048)
#define SMEM_TOTAL_Q (WROW_BYTES + HBUF_BYTES)

__global__ __launch_bounds__(512, 1) void quad_scan(QuadArgs a) {
    extern __shared__ char smem[];
    char* wrow_b = smem;
    char* hbuf_b = smem + WROW_BYTES;

    const int tid = threadIdx.x;
    const int w = tid >> 5, L = tid & 31;
    const int bid = blockIdx.x;
    const size_t HH = (size_t)HID * HID;

    const int l = w >> 2;            // layer of this warp's instances
    const int n0 = (l == 0) ? 3 : 5; // chains per instance
    const int nch = 2 * n0;

    uint4 wreg[NREG][4];
    int chv[10];                     // input-vector id per chain (or -1)

    // ---- init: resolve chains, convert weights to fp16 (regs / SMEM) ----
#pragma unroll
    for (int k = 0; k < 10; k++) {
        chv[k] = -1;
        if (k >= nch) continue;
        const int inst = 2 * w + (k >= n0);
        const int kk = (k < n0) ? k : k - n0;
        const int jf = (bid << 3) + (inst & 7);
        const float* wp;
        if (kk == 0)      wp = a.Wu  + (size_t)l * HH + (size_t)jf * HID;
        else if (kk == 1) wp = a.Wr  + (size_t)l * HH + (size_t)jf * HID;
        else if (kk == 2) wp = a.Wc  + (size_t)l * HH + (size_t)jf * HID;
        else if (kk == 3) wp = a.Uh  + (size_t)(l - 1) * HH + (size_t)jf * HID;
        else              wp = a.Uhr + (size_t)(l - 1) * HH + (size_t)jf * HID;
        chv[k] = (kk < 3) ? l : (l - 1);

        unsigned tmp[16];
        const float* rp = wp + 32 * L;
#pragma unroll
        for (int i = 0; i < 8; i++) {
            float4 f = __ldg((const float4*)rp + i);
            tmp[2 * i]     = pack_h2(f.x, f.y);
            tmp[2 * i + 1] = pack_h2(f.z, f.w);
        }
        if (k < NREG) {
#pragma unroll
            for (int q = 0; q < 4; q++)
                wreg[k][q] = make_uint4(tmp[4 * q], tmp[4 * q + 1],
                                        tmp[4 * q + 2], tmp[4 * q + 3]);
        } else {
            char* rb = wrow_b + (size_t)(w * 6 + (k - NREG)) * 2048;
#pragma unroll
            for (int q = 0; q < 4; q++)
                *(uint4*)(rb + q * 512 + L * 16) =
                    make_uint4(tmp[4 * q], tmp[4 * q + 1],
                               tmp[4 * q + 2], tmp[4 * q + 3]);
        }
    }

    // gate-lane state: lanes 0/1 own instance 2w+L
    const int gj = (bid << 3) + ((2 * w + (L & 1)) & 7);
    float hj = 0.f, bu = 0.f, br = 0.f, bc = 0.f;
    if (L < 2) {
        bu = a.Bu[l * HID + gj]; br = a.Br[l * HID + gj]; bc = a.Bc[l * HID + gj];
    }
    int* const relctr = a.ctr + l * (NSLOT * CSTRIDE) + (bid & (NSLOT - 1)) * CSTRIDE;
    __syncthreads();

    for (int R = 0; R < SEQ + 3; R++) {
        const int t = R - l;
        const bool act = (t >= 0 && t < SEQ);

        // prefetch layer-0 gate input terms
        float zu = 0.f, zr = 0.f, zc = 0.f;
        if (l == 0 && L < 2 && act) {
            zu = __ldg(a.Zu + (size_t)t * HID + gj);
            zr = __ldg(a.Zr + (size_t)t * HID + gj);
            zc = __ldg(a.Zc + (size_t)t * HID + gj);
        }

        // stage: warp v=w (<4) RAW-copies fp16 row h_v(R-1-v) into buf[R&1]
        char* hbR = hbuf_b + (R & 1) * (4 * 2048);
        if (w < 4) {
            char* hb = hbR + w * 2048;
            if (R >= w + 1) {
                int row = R - 1 - w; if (row > SEQ - 1) row = SEQ - 1;
                int tgt = R - w;     if (tgt > SEQ) tgt = SEQ;
                tgt *= 64;
                if (L < NSLOT) {
                    const int* cp = a.ctr + w * (NSLOT * CSTRIDE) + L * CSTRIDE;
                    while (ldacq(cp) < tgt) { }
                }
                __syncwarp();
                const uint4* hr = (const uint4*)(a.H + ((size_t)w * SEQ + row) * HID) + L * 4;
                uint4 hv0 = ldcg4u(hr + 0);
                uint4 hv1 = ldcg4u(hr + 1);
                uint4 hv2 = ldcg4u(hr + 2);
                uint4 hv3 = ldcg4u(hr + 3);
                *(uint4*)(hb + 0 * 512 + L * 16) = hv0;
                *(uint4*)(hb + 1 * 512 + L * 16) = hv1;
                *(uint4*)(hb + 2 * 512 + L * 16) = hv2;
                *(uint4*)(hb + 3 * 512 + L * 16) = hv3;
            } else {
                const uint4 z = make_uint4(0, 0, 0, 0);
#pragma unroll
                for (int q = 0; q < 4; q++) *(uint4*)(hb + q * 512 + L * 16) = z;
            }
        }
        __syncthreads();   // single barrier per round

        if (act) {
            // cache this layer's h vector (majority input)
            uint4 hc[4];
#pragma unroll
            for (int q = 0; q < 4; q++)
                hc[q] = *(const uint4*)(hbR + l * 2048 + q * 512 + L * 16);

            float s[10];
#pragma unroll
            for (int k = 0; k < 10; k++) {
                if (chv[k] < 0) { s[k] = 0.f; continue; }
                const int v = chv[k];
                float x = 0.f;
#pragma unroll
                for (int q = 0; q < 4; q++) {
                    uint4 hg;
                    if (v == l) hg = hc[q];
                    else hg = *(const uint4*)(hbR + v * 2048 + q * 512 + L * 16);
                    uint4 wg;
                    if (k < NREG) wg = wreg[k][q];
                    else wg = *(const uint4*)(wrow_b + (size_t)(w * 6 + (k - NREG)) * 2048 + q * 512 + L * 16);
                    x += dot4u(wg, hg);
                }
                x += __shfl_xor_sync(0xffffffffu, x, 16);
                x += __shfl_xor_sync(0xffffffffu, x, 8);
                x += __shfl_xor_sync(0xffffffffu, x, 4);
                x += __shfl_xor_sync(0xffffffffu, x, 2);
                x += __shfl_xor_sync(0xffffffffu, x, 1);
                s[k] = x;
            }

            // inline gates: lanes 0/1 for instances 2w, 2w+1
            if (L < 2) {
                const int base = (L & 1) * n0;
                float u, r, c;
                if (l == 0) {
                    u = sigf(s[base + 0] + zu + bu);
                    r = sigf(s[base + 1] + zr + br);
                    c = sigf(zc + r * s[base + 2] + bc);
                } else {
                    const float sh5 = s[base + 3], qh5 = s[base + 4];
                    u = sigf(sh5 + s[base + 0] + bu);   // shared Uh term feeds u...
                    r = sigf(qh5 + s[base + 1] + br);
                    c = sigf(sh5 + r * s[base + 2] + bc);  // ...and c (aliased)
                }
                hj = fmaf(u, hj - c, c);
                stcg_h(a.H + ((size_t)l * SEQ + t) * HID + gj, __float2half_rn(hj));
                red_release_add(relctr, 1);
                if (t == SEQ - 1) a.out[l * HID + gj] = hj;
            }
        }
    }
}

// ---------------- launch ----------------
extern "C" void kernel_launch(void* const* d_in, const int* in_sizes, int n_in,
                              void* d_out, int out_size) {
    const float* x   = (const float*)d_in[0];
    const float* Uu  = (const float*)d_in[1];
    const float* Ur  = (const float*)d_in[2];
    const float* U   = (const float*)d_in[3];
    const float* Wu  = (const float*)d_in[4];
    const float* Wr  = (const float*)d_in[5];
    const float* W   = (const float*)d_in[6];
    const float* Bu  = (const float*)d_in[7];
    const float* Br  = (const float*)d_in[8];
    const float* B   = (const float*)d_in[9];
    const float* Uhr = (const float*)d_in[10];
    const float* Uh  = (const float*)d_in[11];
    float* out = (float*)d_out;

    float *Zu, *Zr, *Zc;
    __half* Hh;
    int* ct;
    cudaGetSymbolAddress((void**)&Zu, g_Zu);
    cudaGetSymbolAddress((void**)&Zr, g_Zr);
    cudaGetSymbolAddress((void**)&Zc, g_Zc);
    cudaGetSymbolAddress((void**)&Hh, g_Hh);
    cudaGetSymbolAddress((void**)&ct, g_ctr);

    cudaFuncSetAttribute(quad_scan, cudaFuncAttributeMaxDynamicSharedMemorySize,
                         SMEM_TOTAL_Q);

    reset_ctrs_kernel<<<(4 * NSLOT * CSTRIDE + 255) / 256, 256>>>();

    {   // layer 0 input projections
        dim3 gg(HID / 128, SEQ / 128, 3);
        GemmJob A0{x, Uu, Zu}, B0{x, Ur, Zr}, C0{x, U, Zc};
        sgemm_nt_batch<<<gg, 256>>>(A0, B0, C0);
    }

    QuadArgs q;
    q.Wu = Wu; q.Wr = Wr; q.Wc = W;
    q.Bu = Bu; q.Br = Br; q.Bc = B;
    q.Uh = Uh; q.Uhr = Uhr;
    q.Zu = Zu; q.Zr = Zr; q.Zc = Zc;
    q.H = Hh; q.out = out; q.ctr = ct;
    quad_scan<<<NCTA, 512, SMEM_TOTAL_Q>>>(q);

    (void)in_sizes; (void)n_in; (void)out_size;
}

// round 15
// speedup vs baseline: 1.0342x; 1.0342x over previous
#include <cuda_runtime.h>
#include <cuda_fp16.h>

#define SEQ 4096
#define HID 1024
#define NCTA 128
#define CSTRIDE 32
#define NSLOT 16
#define NCH 9            // chains per warp; 16 warps x 9 = 144 chains
#define NREG 4           // register-resident chains per warp (rest in SMEM)

// ---------------- device scratch ----------------
__device__ float  g_Zu[SEQ * HID];
__device__ float  g_Zr[SEQ * HID];
__device__ float  g_Zc[SEQ * HID];
__device__ __half g_Hh[4][SEQ * HID];      // fp16 hidden-state exchange
__device__ int    g_ctr[4][NSLOT * CSTRIDE];

__global__ void reset_ctrs_kernel() {
    int i = blockIdx.x * blockDim.x + threadIdx.x;
    if (i < 4 * NSLOT * CSTRIDE) ((int*)g_ctr)[i] = 0;
}

// ---------------- memory helpers (proven sync primitives) ----------------
__device__ __forceinline__ uint4 ldcg4u(const uint4* p) {
    uint4 v;
    asm volatile("ld.global.cg.v4.u32 {%0,%1,%2,%3},[%4];"
                 : "=r"(v.x), "=r"(v.y), "=r"(v.z), "=r"(v.w) : "l"(p) : "memory");
    return v;
}
__device__ __forceinline__ void stcg_h(__half* p, __half v) {
    unsigned short b = *(unsigned short*)&v;
    asm volatile("st.global.cg.u16 [%0],%1;" :: "l"(p), "h"(b) : "memory");
}
__device__ __forceinline__ int ldacq(const int* p) {
    int v;
    asm volatile("ld.acquire.gpu.global.s32 %0,[%1];" : "=r"(v) : "l"(p) : "memory");
    return v;
}
__device__ __forceinline__ void red_release_add(int* p, int v) {
    asm volatile("red.release.gpu.global.add.s32 [%0],%1;" :: "l"(p), "r"(v) : "memory");
}
__device__ __forceinline__ float sigf(float x) { return 1.f / (1.f + __expf(-x)); }

__device__ __forceinline__ unsigned pack_h2(float a, float b) {
    __half2 h = __floats2half2_rn(a, b);
    return *(unsigned*)&h;
}
// fp16 SIMD dot of 8 elems, fp32 result
__device__ __forceinline__ float dot4u(const uint4& wv, const uint4& hv) {
    const __half2* w = (const __half2*)&wv;
    const __half2* h = (const __half2*)&hv;
    __half2 acc = __hmul2(w[0], h[0]);
    acc = __hfma2(w[1], h[1], acc);
    acc = __hfma2(w[2], h[2], acc);
    acc = __hfma2(w[3], h[3], acc);
    float2 f = __half22float2(acc);
    return f.x + f.y;
}

// ---------------- fp32 SGEMM batch (layer-0 input projections) -------------
struct GemmJob { const float* A; const float* B; float* C; };
__global__ __launch_bounds__(256) void sgemm_nt_batch(GemmJob j0, GemmJob j1, GemmJob j2) {
    const GemmJob job = (blockIdx.z == 0) ? j0 : (blockIdx.z == 1) ? j1 : j2;
    const float* __restrict__ A = job.A;
    const float* __restrict__ B = job.B;
    float* __restrict__ C = job.C;
    const int K = HID, N = HID;
    __shared__ float As[8][128];
    __shared__ float Bs[8][128];
    const int tid = threadIdx.x;
    const int m0 = blockIdx.y * 128;
    const int n0 = blockIdx.x * 128;
    const int tx = tid & 15;
    const int ty = tid >> 4;
    const int lrow = tid >> 1;
    const int kp = (tid & 1) * 4;

    const float* Ap = A + (m0 + lrow) * K + kp;
    const float* Bp = B + (n0 + lrow) * K + kp;

    float acc[8][8];
#pragma unroll
    for (int i = 0; i < 8; i++)
#pragma unroll
        for (int j = 0; j < 8; j++) acc[i][j] = 0.f;

    for (int k0 = 0; k0 < K; k0 += 8) {
        float4 av = *(const float4*)(Ap + k0);
        float4 bv = *(const float4*)(Bp + k0);
        __syncthreads();
        As[kp + 0][lrow] = av.x; As[kp + 1][lrow] = av.y;
        As[kp + 2][lrow] = av.z; As[kp + 3][lrow] = av.w;
        Bs[kp + 0][lrow] = bv.x; Bs[kp + 1][lrow] = bv.y;
        Bs[kp + 2][lrow] = bv.z; Bs[kp + 3][lrow] = bv.w;
        __syncthreads();
#pragma unroll
        for (int kk = 0; kk < 8; kk++) {
            float a[8], b[8];
#pragma unroll
            for (int i = 0; i < 8; i++) a[i] = As[kk][ty * 8 + i];
#pragma unroll
            for (int j = 0; j < 8; j++) b[j] = Bs[kk][tx * 8 + j];
#pragma unroll
            for (int i = 0; i < 8; i++)
#pragma unroll
                for (int j = 0; j < 8; j++) acc[i][j] = fmaf(a[i], b[j], acc[i][j]);
        }
    }
#pragma unroll
    for (int i = 0; i < 8; i++) {
        float* Cp = C + (m0 + ty * 8 + i) * N + n0 + tx * 8;
#pragma unroll
        for (int j = 0; j < 8; j++) Cp[j] = acc[i][j];
    }
}

// ---------------- quad-layer fused GRU scan ----------------
// 128 CTAs x 512 threads (16 warps), 9 chains/warp (NREG in regs, 5 in SMEM,
// conflict-free transposed layout q*512+L*16). Round R: layer l does t=R-l.
// Warps 0-3 poll + RAW-copy fp16 h rows into SMEM; barA; all warps compute
// 9 dots, then STAGE-BATCHED shfl reduce (9 independent shfls per stage ->
// short serial tail); lanes 0-3 write 4 partials per chain to res4; barB;
// warps 12-15 (one layer each, lanes 0-7) sum partials, gates, fp16 store,
// red.release.
struct QuadArgs {
    const float *Wu, *Wr, *Wc, *Bu, *Br, *Bc, *Uh, *Uhr, *Zu, *Zr, *Zc;
    __half *H;
    float *out;
    int *ctr;
};

#define WROW_BYTES (80 * 2048)
#define HBUF_BYTES (4 * 2048)
#define RES4_BYTES (160 * 4 * 4)
#define SMEM_TOTAL_Q (WROW_BYTES + HBUF_BYTES + RES4_BYTES)

__global__ __launch_bounds__(512, 1) void quad_scan(QuadArgs a) {
    extern __shared__ char smem[];
    char*  wrow_b = smem;
    char*  hbuf_b = smem + WROW_BYTES;
    float* res4   = (float*)(smem + WROW_BYTES + HBUF_BYTES);

    const int tid = threadIdx.x;
    const int w = tid >> 5, L = tid & 31;
    const int bid = blockIdx.x;
    const size_t HH = (size_t)HID * HID;

    const int c4 = w * NCH + 4;
    const int vMaj = (c4 < 40) ? 0 : (c4 < 80) ? 1 : (c4 < 120) ? 2 : 3;

    uint4 wreg[NREG][4];
    int meta[NCH];

    // ---- init: resolve chains, convert weights to fp16 (regs / SMEM) ----
#pragma unroll
    for (int k = 0; k < NCH; k++) {
        const int c = w * NCH + k;
        const int v = (c < 40) ? 0 : (c < 80) ? 1 : (c < 120) ? 2 : 3;
        const int g = c - 40 * v;
        int l, j, kind;
        if (v == 3 || g < 24) { l = v; j = g / 3; kind = g - 3 * j; }
        else { const int gg = g - 24; l = v + 1; j = gg >> 1; kind = 3 + (gg & 1); }
        const int jf = (bid << 3) + j;
        const float* wp;
        if (kind == 0)      wp = a.Wu  + (size_t)l * HH + (size_t)jf * HID;
        else if (kind == 1) wp = a.Wr  + (size_t)l * HH + (size_t)jf * HID;
        else if (kind == 2) wp = a.Wc  + (size_t)l * HH + (size_t)jf * HID;
        else if (kind == 3) wp = a.Uh  + (size_t)(l - 1) * HH + (size_t)jf * HID;
        else                wp = a.Uhr + (size_t)(l - 1) * HH + (size_t)jf * HID;
        const int roff = (l * 8 + j) * 5 + kind;
        meta[k] = l | (((v == vMaj) ? 1 : 0) << 2) | (v << 3) | (roff << 5);

        unsigned tmp[16];
        const float* rp = wp + 32 * L;
#pragma unroll
        for (int i = 0; i < 8; i++) {
            float4 f = __ldg((const float4*)rp + i);
            tmp[2 * i]     = pack_h2(f.x, f.y);
            tmp[2 * i + 1] = pack_h2(f.z, f.w);
        }
        if (k < NREG) {
#pragma unroll
            for (int q = 0; q < 4; q++)
                wreg[k][q] = make_uint4(tmp[4 * q], tmp[4 * q + 1],
                                        tmp[4 * q + 2], tmp[4 * q + 3]);
        } else {
            char* rb = wrow_b + (size_t)(w * 5 + (k - NREG)) * 2048;
#pragma unroll
            for (int q = 0; q < 4; q++)
                *(uint4*)(rb + q * 512 + L * 16) =
                    make_uint4(tmp[4 * q], tmp[4 * q + 1],
                               tmp[4 * q + 2], tmp[4 * q + 3]);
        }
    }

    // gate-warp state: warp 12+gl handles layer gl, lanes 0-7 = outputs
    const int gl = w - 12;                     // valid when w >= 12
    const int gj = (bid << 3) + (L & 7);
    float hj = 0.f, bu = 0.f, br = 0.f, bc = 0.f;
    if (w >= 12 && L < 8) {
        bu = a.Bu[gl * HID + gj]; br = a.Br[gl * HID + gj]; bc = a.Bc[gl * HID + gj];
    }
    int* relctr = nullptr;
    if (w >= 12)
        relctr = a.ctr + gl * (NSLOT * CSTRIDE) + (bid & (NSLOT - 1)) * CSTRIDE;
    __syncthreads();

    for (int R = 0; R < SEQ + 3; R++) {
        // prefetch layer-0 gate input terms (warp 12, lanes 0-7)
        float zu = 0.f, zr = 0.f, zc = 0.f;
        if (w == 12 && L < 8 && R < SEQ) {
            zu = __ldg(a.Zu + (size_t)R * HID + gj);
            zr = __ldg(a.Zr + (size_t)R * HID + gj);
            zc = __ldg(a.Zc + (size_t)R * HID + gj);
        }
        // stage: warp l RAW-copies fp16 row h_l(R-1-l) into transposed SMEM
        if (w < 4) {
            const int l = w;
            char* hb = hbuf_b + l * 2048;
            if (R >= l + 1) {
                int row = R - 1 - l; if (row > SEQ - 1) row = SEQ - 1;
                int tgt = R - l;     if (tgt > SEQ) tgt = SEQ;
                tgt *= 64;
                if (L < NSLOT) {
                    const int* cp = a.ctr + l * (NSLOT * CSTRIDE) + L * CSTRIDE;
                    while (ldacq(cp) < tgt) { }
                }
                __syncwarp();
                const uint4* hr = (const uint4*)(a.H + ((size_t)l * SEQ + row) * HID) + L * 4;
                uint4 hv0 = ldcg4u(hr + 0);
                uint4 hv1 = ldcg4u(hr + 1);
                uint4 hv2 = ldcg4u(hr + 2);
                uint4 hv3 = ldcg4u(hr + 3);
                *(uint4*)(hb + 0 * 512 + L * 16) = hv0;
                *(uint4*)(hb + 1 * 512 + L * 16) = hv1;
                *(uint4*)(hb + 2 * 512 + L * 16) = hv2;
                *(uint4*)(hb + 3 * 512 + L * 16) = hv3;
            } else {
                const uint4 z = make_uint4(0, 0, 0, 0);
#pragma unroll
                for (int q = 0; q < 4; q++) *(uint4*)(hb + q * 512 + L * 16) = z;
            }
        }
        __syncthreads();   // bar A

        uint4 hc[4];
#pragma unroll
        for (int q = 0; q < 4; q++)
            hc[q] = *(const uint4*)(hbuf_b + vMaj * 2048 + q * 512 + L * 16);

        // phase 1: all 9 dots (independent FMA streams, tree-added)
        float x[NCH];
#pragma unroll
        for (int k = 0; k < NCH; k++) {
            const int m = meta[k];
            const int l = m & 3;
            const int t = R - l;
            if (t < 0 || t >= SEQ) { x[k] = 0.f; continue; }
            const bool cached = (m >> 2) & 1;
            const int v = (m >> 3) & 3;
            float d[4];
#pragma unroll
            for (int q = 0; q < 4; q++) {
                uint4 hg;
                if (cached) hg = hc[q];
                else hg = *(const uint4*)(hbuf_b + v * 2048 + q * 512 + L * 16);
                uint4 wg;
                if (k < NREG) wg = wreg[k][q];
                else wg = *(const uint4*)(wrow_b + (size_t)(w * 5 + (k - NREG)) * 2048 + q * 512 + L * 16);
                d[q] = dot4u(wg, hg);
            }
            x[k] = (d[0] + d[1]) + (d[2] + d[3]);
        }
        // phase 2: stage-batched reduce (independent shfls per stage)
#pragma unroll
        for (int k = 0; k < NCH; k++) x[k] += __shfl_xor_sync(0xffffffffu, x[k], 16);
#pragma unroll
        for (int k = 0; k < NCH; k++) x[k] += __shfl_xor_sync(0xffffffffu, x[k], 8);
#pragma unroll
        for (int k = 0; k < NCH; k++) x[k] += __shfl_xor_sync(0xffffffffu, x[k], 4);
        if (L < 4) {
#pragma unroll
            for (int k = 0; k < NCH; k++) {
                const int m = meta[k];
                const int t = R - (m & 3);
                if (t >= 0 && t < SEQ) res4[(m >> 5) * 4 + L] = x[k];
            }
        }
        __syncthreads();   // bar B

        // gates: warps 12-15, lanes 0-7, layer gl = w-12
        if (w >= 12 && L < 8) {
            const int t = R - gl;
            if (t >= 0 && t < SEQ) {
                const int ibase = (gl * 8 + (L & 7)) * 5;
                const float4 p0 = *(const float4*)(res4 + (ibase + 0) * 4);
                const float4 p1 = *(const float4*)(res4 + (ibase + 1) * 4);
                const float4 p2 = *(const float4*)(res4 + (ibase + 2) * 4);
                const float r0 = (p0.x + p0.y) + (p0.z + p0.w);
                const float r1 = (p1.x + p1.y) + (p1.z + p1.w);
                const float r2 = (p2.x + p2.y) + (p2.z + p2.w);
                float u, r, c;
                if (gl == 0) {
                    u = sigf(r0 + zu + bu);
                    r = sigf(r1 + zr + br);
                    c = sigf(zc + r * r2 + bc);
                } else {
                    const float4 p3 = *(const float4*)(res4 + (ibase + 3) * 4);
                    const float4 p4 = *(const float4*)(res4 + (ibase + 4) * 4);
                    const float s5 = (p3.x + p3.y) + (p3.z + p3.w);
                    const float q5 = (p4.x + p4.y) + (p4.z + p4.w);
                    u = sigf(s5 + r0 + bu);       // shared Uh term feeds u...
                    r = sigf(q5 + r1 + br);
                    c = sigf(s5 + r * r2 + bc);   // ...and c (aliased parameter)
                }
                hj = fmaf(u, hj - c, c);
                stcg_h(a.H + ((size_t)gl * SEQ + t) * HID + gj, __float2half_rn(hj));
                red_release_add(relctr, 1);
                if (t == SEQ - 1) a.out[gl * HID + gj] = hj;
            }
        }
    }
}

// ---------------- launch ----------------
extern "C" void kernel_launch(void* const* d_in, const int* in_sizes, int n_in,
                              void* d_out, int out_size) {
    const float* x   = (const float*)d_in[0];
    const float* Uu  = (const float*)d_in[1];
    const float* Ur  = (const float*)d_in[2];
    const float* U   = (const float*)d_in[3];
    const float* Wu  = (const float*)d_in[4];
    const float* Wr  = (const float*)d_in[5];
    const float* W   = (const float*)d_in[6];
    const float* Bu  = (const float*)d_in[7];
    const float* Br  = (const float*)d_in[8];
    const float* B   = (const float*)d_in[9];
    const float* Uhr = (const float*)d_in[10];
    const float* Uh  = (const float*)d_in[11];
    float* out = (float*)d_out;

    float *Zu, *Zr, *Zc;
    __half* Hh;
    int* ct;
    cudaGetSymbolAddress((void**)&Zu, g_Zu);
    cudaGetSymbolAddress((void**)&Zr, g_Zr);
    cudaGetSymbolAddress((void**)&Zc, g_Zc);
    cudaGetSymbolAddress((void**)&Hh, g_Hh);
    cudaGetSymbolAddress((void**)&ct, g_ctr);

    cudaFuncSetAttribute(quad_scan, cudaFuncAttributeMaxDynamicSharedMemorySize,
                         SMEM_TOTAL_Q);

    reset_ctrs_kernel<<<(4 * NSLOT * CSTRIDE + 255) / 256, 256>>>();

    {   // layer 0 input projections
        dim3 gg(HID / 128, SEQ / 128, 3);
        GemmJob A0{x, Uu, Zu}, B0{x, Ur, Zr}, C0{x, U, Zc};
        sgemm_nt_batch<<<gg, 256>>>(A0, B0, C0);
    }

    QuadArgs q;
    q.Wu = Wu; q.Wr = Wr; q.Wc = W;
    q.Bu = Bu; q.Br = Br; q.Bc = B;
    q.Uh = Uh; q.Uhr = Uhr;
    q.Zu = Zu; q.Zr = Zr; q.Zc = Zc;
    q.H = Hh; q.out = out; q.ctr = ct;
    quad_scan<<<NCTA, 512, SMEM_TOTAL_Q>>>(q);

    (void)in_sizes; (void)n_in; (void)out_size;
}